// round 4
// baseline (speedup 1.0000x reference)
#include <cuda_runtime.h>
#include <cuda_fp16.h>
#include <cstdint>

#define HH 64
#define WW 64
#define PP 4096          // HH*WW
#define CC 21
#define CPAD 24
#define NB 2
#define KS 71
#define KR 35

// ---------------- scratch (static device globals; no allocation) ----------------
__device__ __align__(16) __half  d_Kh[(size_t)NB * PP * PP];    // 64 MiB K hi
__device__ __align__(16) __half  d_Kl[(size_t)NB * PP * PP];    // 64 MiB K lo (residual)
__device__ __align__(16) float   d_feats[NB * PP * 5];
__device__ __align__(16) float   d_U[NB * CC * PP];
__device__ __align__(16) float   d_q[NB * CC * PP];
__device__ __align__(16) __half  d_Vh[(size_t)NB * PP * CPAD];  // q probs fp16 hi, padded
__device__ __align__(16) __half  d_Vl[(size_t)NB * PP * CPAD];  // q probs fp16 lo
__device__ __align__(16) float   d_qbf[NB * CC * PP];
__device__ __align__(16) float   d_tmp[NB * CC * PP];
__device__ float                 d_g1d[KS];

// ---------------- cp.async helpers ----------------
#define CP_ASYNC16(smem_u32, gptr) \
    asm volatile("cp.async.cg.shared.global [%0], [%1], 16;\n" :: "r"(smem_u32), "l"(gptr) : "memory")
#define CP_COMMIT()  asm volatile("cp.async.commit_group;\n" ::: "memory")
#define CP_WAIT1()   asm volatile("cp.async.wait_group 1;\n" ::: "memory")

__device__ __forceinline__ void split_half(float v, __half& hi, __half& lo) {
    hi = __float2half(v);
    lo = __float2half(v - __half2float(hi));
}

// ---------------- prep: features ----------------
__global__ void feats_kernel(const float* __restrict__ ref, const float* __restrict__ kstd) {
    int idx = blockIdx.x * blockDim.x + threadIdx.x;
    if (idx >= NB * PP) return;
    int n = idx / PP, p = idx % PP;
    int y = p / WW, x = p % WW;
    const float* r = ref + (size_t)n * 3 * PP + p;
    d_feats[idx * 5 + 0] = (float)y / kstd[0];
    d_feats[idx * 5 + 1] = (float)x / kstd[1];
    d_feats[idx * 5 + 2] = r[0]        / kstd[2];
    d_feats[idx * 5 + 3] = r[PP]       / kstd[3];
    d_feats[idx * 5 + 4] = r[2 * PP]   / kstd[4];
}

// ---------------- prep: 1-D separable Gaussian from gk ----------------
// gk[0,0,i,j] = g[i]*g[j], sum(g)=1  =>  g[i] = gk[i][KR] / sqrt(gk[KR][KR])
__global__ void g1d_kernel(const float* __restrict__ gk) {
    int i = threadIdx.x;
    if (i < KS) {
        float center = gk[KR * KS + KR];
        d_g1d[i] = gk[i * KS + KR] * rsqrtf(center);
    }
}

// ---------------- prep: U = log(clip(unary)), q = softmax_C(U) ----------------
__global__ void init_kernel(const float* __restrict__ unary) {
    int idx = blockIdx.x * blockDim.x + threadIdx.x;
    if (idx >= NB * PP) return;
    int n = idx / PP, p = idx % PP;
    const float* u = unary + (size_t)n * CC * PP + p;
    float lg[CC];
    float m = -1e30f;
    #pragma unroll
    for (int c = 0; c < CC; ++c) {
        float v = u[(size_t)c * PP];
        v = fminf(fmaxf(v, 1e-5f), 1.0f);
        v = logf(v);
        lg[c] = v;
        m = fmaxf(m, v);
        d_U[((size_t)n * CC + c) * PP + p] = v;
    }
    float s = 0.f;
    #pragma unroll
    for (int c = 0; c < CC; ++c) { float e = expf(lg[c] - m); lg[c] = e; s += e; }
    float inv = 1.f / s;
    __half* vh = d_Vh + ((size_t)n * PP + p) * CPAD;
    __half* vl = d_Vl + ((size_t)n * PP + p) * CPAD;
    #pragma unroll
    for (int c = 0; c < CC; ++c) {
        float qv = lg[c] * inv;
        d_q[((size_t)n * CC + c) * PP + p] = qv;
        split_half(qv, vh[c], vl[c]);
    }
    #pragma unroll
    for (int c = CC; c < CPAD; ++c) { vh[c] = __float2half(0.f); vl[c] = __float2half(0.f); }
}

// ---------------- build K (fp16 hi+lo), tiled 64x64 ----------------
__global__ void buildK_kernel() {
    __shared__ float fp[64][5];
    __shared__ float fq[64][5];
    int n  = blockIdx.z;
    int p0 = blockIdx.y * 64;
    int q0 = blockIdx.x * 64;
    int tx = threadIdx.x, ty = threadIdx.y;
    int tid = ty * 64 + tx;
    for (int i = tid; i < 320; i += 256) {
        (&fp[0][0])[i] = d_feats[((size_t)n * PP + p0) * 5 + i];
        (&fq[0][0])[i] = d_feats[((size_t)n * PP + q0) * 5 + i];
    }
    __syncthreads();
    float f0 = fq[tx][0], f1 = fq[tx][1], f2 = fq[tx][2], f3 = fq[tx][3], f4 = fq[tx][4];
    #pragma unroll 4
    for (int r = ty; r < 64; r += 4) {
        float a = fp[r][0] - f0, b = fp[r][1] - f1, c = fp[r][2] - f2,
              d = fp[r][3] - f3, e = fp[r][4] - f4;
        float dd = a * a + b * b + c * c + d * d + e * e;
        float k  = __expf(-0.5f * dd);
        size_t o = ((size_t)(n * PP + p0 + r)) * PP + q0 + tx;
        __half hi, lo;
        split_half(k, hi, lo);
        d_Kh[o] = hi;
        d_Kl[o] = lo;
    }
}

// ---- GEMM: qbf[c,p] = sum_q K[p,q]*V[q,c], compensated fp16 (3-term Markidis) ----
// A smem layout: 64 rows x 8 segments of 16B (stride 128B, always 16B-aligned);
// segment index XOR-swizzled by (row & 7) to spread banks — no padding needed.
#define BM 64
#define KC 64
#define NCHUNK (PP / KC)   // 64

__global__ __launch_bounds__(128) void gemm_kernel() {
    __shared__ __align__(16) __half Ash[2][BM][KC];      // 16384 B
    __shared__ __align__(16) __half Asl[2][BM][KC];      // 16384 B
    __shared__ __align__(16) __half Bsh[2][KC][CPAD];    // 6144 B
    __shared__ __align__(16) __half Bsl[2][KC][CPAD];    // 6144 B  (total 45056)

    int n  = blockIdx.y;
    int p0 = blockIdx.x * BM;
    int tid = threadIdx.x;
    int warp = tid >> 5, lane = tid & 31;

    const __half* Khb = d_Kh + (size_t)n * PP * PP;
    const __half* Klb = d_Kl + (size_t)n * PP * PP;
    const __half* Vhb = d_Vh + (size_t)n * PP * CPAD;
    const __half* Vlb = d_Vl + (size_t)n * PP * CPAD;

    float acc[3][4];
    #pragma unroll
    for (int i = 0; i < 3; ++i)
        #pragma unroll
        for (int j = 0; j < 4; ++j) acc[i][j] = 0.f;

    auto load_stage = [&](int chunk, int buf) {
        int q0 = chunk * KC;
        #pragma unroll
        for (int i = 0; i < 4; ++i) {               // A: 64 rows x 8 segs(16B) x {h,l}
            int idx = tid * 4 + i;                  // 0..511
            int row = idx >> 3, seg = idx & 7;
            int pseg = seg ^ (row & 7);             // XOR swizzle
            const __half* gh = Khb + (size_t)(p0 + row) * PP + q0 + seg * 8;
            const __half* gl = Klb + (size_t)(p0 + row) * PP + q0 + seg * 8;
            CP_ASYNC16((uint32_t)__cvta_generic_to_shared(&Ash[buf][row][pseg * 8]), gh);
            CP_ASYNC16((uint32_t)__cvta_generic_to_shared(&Asl[buf][row][pseg * 8]), gl);
        }
        #pragma unroll
        for (int i = 0; i < 2; ++i) {               // B: 64*24 halves = 192 segs x {h,l}
            int idx = tid * 2 + i;                  // 0..255, guard <192
            if (idx < 192) {
                const __half* gh = Vhb + (size_t)q0 * CPAD + idx * 8;
                const __half* gl = Vlb + (size_t)q0 * CPAD + idx * 8;
                CP_ASYNC16((uint32_t)__cvta_generic_to_shared(&Bsh[buf][0][0] + idx * 8), gh);
                CP_ASYNC16((uint32_t)__cvta_generic_to_shared(&Bsl[buf][0][0] + idx * 8), gl);
            }
        }
    };

    load_stage(0, 0);
    CP_COMMIT();

    for (int ch = 0; ch < NCHUNK; ++ch) {
        int buf = ch & 1;
        if (ch + 1 < NCHUNK) load_stage(ch + 1, buf ^ 1);
        CP_COMMIT();
        CP_WAIT1();
        __syncthreads();

        int m0 = warp * 16;
        #pragma unroll
        for (int kk = 0; kk < KC / 16; ++kk) {
            int arow = m0 + (lane & 15);
            int aseg = (kk * 2 + (lane >> 4)) ^ (arow & 7);   // swizzled segment
            uint32_t ah0, ah1, ah2, ah3, al0, al1, al2, al3;
            uint32_t aaddr_h = (uint32_t)__cvta_generic_to_shared(&Ash[buf][arow][aseg * 8]);
            uint32_t aaddr_l = (uint32_t)__cvta_generic_to_shared(&Asl[buf][arow][aseg * 8]);
            asm volatile("ldmatrix.sync.aligned.m8n8.x4.shared.b16 {%0,%1,%2,%3}, [%4];"
                         : "=r"(ah0), "=r"(ah1), "=r"(ah2), "=r"(ah3) : "r"(aaddr_h));
            asm volatile("ldmatrix.sync.aligned.m8n8.x4.shared.b16 {%0,%1,%2,%3}, [%4];"
                         : "=r"(al0), "=r"(al1), "=r"(al2), "=r"(al3) : "r"(aaddr_l));
            #pragma unroll
            for (int nt = 0; nt < 3; ++nt) {
                uint32_t bh0, bh1, bl0, bl1;
                uint32_t baddr_h = (uint32_t)__cvta_generic_to_shared(
                    &Bsh[buf][kk * 16 + (lane & 15)][nt * 8]);
                uint32_t baddr_l = (uint32_t)__cvta_generic_to_shared(
                    &Bsl[buf][kk * 16 + (lane & 15)][nt * 8]);
                asm volatile("ldmatrix.sync.aligned.m8n8.x2.trans.shared.b16 {%0,%1}, [%2];"
                             : "=r"(bh0), "=r"(bh1) : "r"(baddr_h));
                asm volatile("ldmatrix.sync.aligned.m8n8.x2.trans.shared.b16 {%0,%1}, [%2];"
                             : "=r"(bl0), "=r"(bl1) : "r"(baddr_l));
                asm volatile(
                    "mma.sync.aligned.m16n8k16.row.col.f32.f16.f16.f32 "
                    "{%0,%1,%2,%3}, {%4,%5,%6,%7}, {%8,%9}, {%0,%1,%2,%3};"
                    : "+f"(acc[nt][0]), "+f"(acc[nt][1]), "+f"(acc[nt][2]), "+f"(acc[nt][3])
                    : "r"(ah0), "r"(ah1), "r"(ah2), "r"(ah3), "r"(bh0), "r"(bh1));
                asm volatile(
                    "mma.sync.aligned.m16n8k16.row.col.f32.f16.f16.f32 "
                    "{%0,%1,%2,%3}, {%4,%5,%6,%7}, {%8,%9}, {%0,%1,%2,%3};"
                    : "+f"(acc[nt][0]), "+f"(acc[nt][1]), "+f"(acc[nt][2]), "+f"(acc[nt][3])
                    : "r"(ah0), "r"(ah1), "r"(ah2), "r"(ah3), "r"(bl0), "r"(bl1));
                asm volatile(
                    "mma.sync.aligned.m16n8k16.row.col.f32.f16.f16.f32 "
                    "{%0,%1,%2,%3}, {%4,%5,%6,%7}, {%8,%9}, {%0,%1,%2,%3};"
                    : "+f"(acc[nt][0]), "+f"(acc[nt][1]), "+f"(acc[nt][2]), "+f"(acc[nt][3])
                    : "r"(al0), "r"(al1), "r"(al2), "r"(al3), "r"(bh0), "r"(bh1));
            }
        }
        __syncthreads();
    }

    // epilogue: scatter D
    float* qbf = d_qbf + (size_t)n * CC * PP;
    int prow = p0 + warp * 16 + (lane >> 2);
    int cb = (lane & 3) * 2;
    #pragma unroll
    for (int nt = 0; nt < 3; ++nt)
        #pragma unroll
        for (int r = 0; r < 4; ++r) {
            int c = nt * 8 + cb + (r & 1);
            int p = prow + (r >> 1) * 8;
            if (c < CC) qbf[(size_t)c * PP + p] = acc[nt][r];
        }
}

// ---------------- vertical 1-D conv on q -> tmp ----------------
__global__ void vconv_kernel() {
    int idx = blockIdx.x * blockDim.x + threadIdx.x;
    if (idx >= NB * CC * PP) return;
    int x = idx & 63, y = (idx >> 6) & 63, nc = idx >> 12;
    const float* base = d_q + (size_t)nc * PP;
    int dlo = (35 - y) > 0 ? (35 - y) : 0;
    int dhi = (98 - y) < 70 ? (98 - y) : 70;
    float acc = 0.f;
    for (int d = dlo; d <= dhi; ++d)
        acc += d_g1d[d] * base[(y + d - KR) * WW + x];
    d_tmp[idx] = acc;
}

// ---------------- horizontal conv + combine + softmax ----------------
__global__ __launch_bounds__(64) void hcombine_kernel(float* __restrict__ outp, int write_out) {
    __shared__ float row[CC][WW + 2 * KR];   // zero-padded rows
    __shared__ float g[KS];
    int bn = blockIdx.x;
    int n = bn >> 6, y = bn & 63;
    int x = threadIdx.x;

    for (int i = x; i < KS; i += 64) g[i] = d_g1d[i];
    #pragma unroll
    for (int c = 0; c < CC; ++c) {
        row[c][KR + x] = d_tmp[((size_t)n * CC + c) * PP + y * WW + x];
        if (x < KR) { row[c][x] = 0.f; row[c][KR + WW + x] = 0.f; }
    }
    __syncthreads();

    const float* Ub = d_U   + (size_t)n * CC * PP + y * WW + x;
    const float* Qb = d_qbf + (size_t)n * CC * PP + y * WW + x;
    float lg[CC];
    float m = -1e30f;
    #pragma unroll
    for (int c = 0; c < CC; ++c) {
        float s = 0.f;
        #pragma unroll 7
        for (int d = 0; d < KS; ++d) s += g[d] * row[c][x + d];
        float v = Ub[(size_t)c * PP] + 4.0f * Qb[(size_t)c * PP] + 2.0f * s;
        lg[c] = v;
        m = fmaxf(m, v);
    }
    float ssum = 0.f;
    #pragma unroll
    for (int c = 0; c < CC; ++c) { float e = expf(lg[c] - m); lg[c] = e; ssum += e; }
    float inv = 1.f / ssum;
    __half* vh = d_Vh + ((size_t)n * PP + y * WW + x) * CPAD;
    __half* vl = d_Vl + ((size_t)n * PP + y * WW + x) * CPAD;
    #pragma unroll
    for (int c = 0; c < CC; ++c) {
        float qv = lg[c] * inv;
        size_t o = ((size_t)n * CC + c) * PP + y * WW + x;
        d_q[o] = qv;
        split_half(qv, vh[c], vl[c]);
        if (write_out) outp[o] = qv;
    }
}

// ---------------- launch ----------------
extern "C" void kernel_launch(void* const* d_in, const int* in_sizes, int n_in,
                              void* d_out, int out_size) {
    const float* unary = (const float*)d_in[0];
    const float* ref   = (const float*)d_in[1];
    const float* gk    = (const float*)d_in[2];
    const float* kstd  = (const float*)d_in[3];
    float* out = (float*)d_out;

    feats_kernel<<<(NB * PP + 255) / 256, 256>>>(ref, kstd);
    g1d_kernel<<<1, 128>>>(gk);
    init_kernel<<<(NB * PP + 255) / 256, 256>>>(unary);
    buildK_kernel<<<dim3(PP / 64, PP / 64, NB), dim3(64, 4)>>>();

    for (int it = 0; it < 5; ++it) {
        vconv_kernel<<<(NB * CC * PP + 255) / 256, 256>>>();
        gemm_kernel<<<dim3(PP / BM, NB), 128>>>();
        hcombine_kernel<<<NB * HH, 64>>>(out, it == 4 ? 1 : 0);
    }
}

// round 5
// speedup vs baseline: 1.2474x; 1.2474x over previous
#include <cuda_runtime.h>
#include <cuda_fp16.h>
#include <cstdint>

#define HH 64
#define WW 64
#define PP 4096          // HH*WW
#define CC 21
#define CPAD 24
#define NB 2
#define KS 71
#define KR 35
#define SPLITS 4
#define KRANGE (PP / SPLITS)   // 1024

// ---------------- scratch (static device globals; no allocation) ----------------
__device__ __align__(16) __half  d_Kh[(size_t)NB * PP * PP];    // 64 MiB K hi
__device__ __align__(16) __half  d_Kl[(size_t)NB * PP * PP];    // 64 MiB K lo (residual)
__device__ __align__(16) float   d_feats[NB * PP * 5];
__device__ __align__(16) float   d_U[NB * CC * PP];
__device__ __align__(16) float   d_q[NB * CC * PP];
__device__ __align__(16) __half  d_Vh[(size_t)NB * PP * CPAD];  // q probs fp16 hi, padded
__device__ __align__(16) __half  d_Vl[(size_t)NB * PP * CPAD];  // q probs fp16 lo
__device__ __align__(16) float   d_qbfp[(size_t)SPLITS * NB * CC * PP]; // split-K partials
__device__ __align__(16) float   d_tmp[NB * CC * PP];
__device__ float                 d_g1d[KS];

// ---------------- cp.async helpers ----------------
#define CP_ASYNC16(smem_u32, gptr) \
    asm volatile("cp.async.cg.shared.global [%0], [%1], 16;\n" :: "r"(smem_u32), "l"(gptr) : "memory")
#define CP_COMMIT()  asm volatile("cp.async.commit_group;\n" ::: "memory")
#define CP_WAIT1()   asm volatile("cp.async.wait_group 1;\n" ::: "memory")

__device__ __forceinline__ void split_half(float v, __half& hi, __half& lo) {
    hi = __float2half(v);
    lo = __float2half(v - __half2float(hi));
}

// ---------------- prep: features ----------------
__global__ void feats_kernel(const float* __restrict__ ref, const float* __restrict__ kstd) {
    int idx = blockIdx.x * blockDim.x + threadIdx.x;
    if (idx >= NB * PP) return;
    int n = idx / PP, p = idx % PP;
    int y = p / WW, x = p % WW;
    const float* r = ref + (size_t)n * 3 * PP + p;
    d_feats[idx * 5 + 0] = (float)y / kstd[0];
    d_feats[idx * 5 + 1] = (float)x / kstd[1];
    d_feats[idx * 5 + 2] = r[0]        / kstd[2];
    d_feats[idx * 5 + 3] = r[PP]       / kstd[3];
    d_feats[idx * 5 + 4] = r[2 * PP]   / kstd[4];
}

// ---------------- prep: 1-D separable Gaussian from gk ----------------
__global__ void g1d_kernel(const float* __restrict__ gk) {
    int i = threadIdx.x;
    if (i < KS) {
        float center = gk[KR * KS + KR];
        d_g1d[i] = gk[i * KS + KR] * rsqrtf(center);
    }
}

// ---------------- prep: U = log(clip(unary)), q = softmax_C(U) ----------------
__global__ void init_kernel(const float* __restrict__ unary) {
    int idx = blockIdx.x * blockDim.x + threadIdx.x;
    if (idx >= NB * PP) return;
    int n = idx / PP, p = idx % PP;
    const float* u = unary + (size_t)n * CC * PP + p;
    float lg[CC];
    float m = -1e30f;
    #pragma unroll
    for (int c = 0; c < CC; ++c) {
        float v = u[(size_t)c * PP];
        v = fminf(fmaxf(v, 1e-5f), 1.0f);
        v = logf(v);
        lg[c] = v;
        m = fmaxf(m, v);
        d_U[((size_t)n * CC + c) * PP + p] = v;
    }
    float s = 0.f;
    #pragma unroll
    for (int c = 0; c < CC; ++c) { float e = expf(lg[c] - m); lg[c] = e; s += e; }
    float inv = 1.f / s;
    __half* vh = d_Vh + ((size_t)n * PP + p) * CPAD;
    __half* vl = d_Vl + ((size_t)n * PP + p) * CPAD;
    #pragma unroll
    for (int c = 0; c < CC; ++c) {
        float qv = lg[c] * inv;
        d_q[((size_t)n * CC + c) * PP + p] = qv;
        split_half(qv, vh[c], vl[c]);
    }
    #pragma unroll
    for (int c = CC; c < CPAD; ++c) { vh[c] = __float2half(0.f); vl[c] = __float2half(0.f); }
}

// ---------------- build K (fp16 hi+lo), 32x128 tiles, half2 stores ----------------
__global__ __launch_bounds__(256) void buildK_kernel() {
    __shared__ float fp[32][5];    // p rows
    __shared__ float fq[128][5];   // q cols
    int n  = blockIdx.z;
    int p0 = blockIdx.y * 32;
    int q0 = blockIdx.x * 128;
    int tx = threadIdx.x;          // 0..63 -> 2 q cols each
    int ty = threadIdx.y;          // 0..3
    int tid = ty * 64 + tx;

    for (int i = tid; i < 160; i += 256)
        (&fp[0][0])[i] = d_feats[((size_t)n * PP + p0) * 5 + i];
    for (int i = tid; i < 640; i += 256)
        (&fq[0][0])[i] = d_feats[((size_t)n * PP + q0) * 5 + i];
    __syncthreads();

    int c0 = tx * 2;
    float a00 = fq[c0][0], a01 = fq[c0][1], a02 = fq[c0][2], a03 = fq[c0][3], a04 = fq[c0][4];
    float a10 = fq[c0+1][0], a11 = fq[c0+1][1], a12 = fq[c0+1][2], a13 = fq[c0+1][3], a14 = fq[c0+1][4];

    __half* Khb = d_Kh + (size_t)n * PP * PP;
    __half* Klb = d_Kl + (size_t)n * PP * PP;
    uint32_t off = (uint32_t)(p0 + ty) * PP + (uint32_t)(q0 + c0);

    #pragma unroll 8
    for (int r = ty; r < 32; r += 4, off += 4u * PP) {
        float b0 = fp[r][0], b1 = fp[r][1], b2 = fp[r][2], b3 = fp[r][3], b4 = fp[r][4];
        float x0 = b0 - a00, x1 = b1 - a01, x2 = b2 - a02, x3 = b3 - a03, x4 = b4 - a04;
        float d0 = x0*x0 + x1*x1 + x2*x2 + x3*x3 + x4*x4;
        float y0 = b0 - a10, y1 = b1 - a11, y2 = b2 - a12, y3 = b3 - a13, y4 = b4 - a14;
        float d1 = y0*y0 + y1*y1 + y2*y2 + y3*y3 + y4*y4;
        float k0 = __expf(-0.5f * d0);
        float k1 = __expf(-0.5f * d1);
        __half h0, l0, h1, l1;
        split_half(k0, h0, l0);
        split_half(k1, h1, l1);
        *(__half2*)(Khb + off) = __halves2half2(h0, h1);
        *(__half2*)(Klb + off) = __halves2half2(l0, l1);
    }
}

// ---- GEMM: qbf[c,p] = sum_q K[p,q]*V[q,c], compensated fp16, split-K ----
#define BM 64
#define KC 64
#define NCH (KRANGE / KC)   // 16

__global__ __launch_bounds__(128) void gemm_kernel() {
    __shared__ __align__(16) __half Ash[2][BM][KC];      // 16384 B
    __shared__ __align__(16) __half Asl[2][BM][KC];      // 16384 B
    __shared__ __align__(16) __half Bsh[2][KC][CPAD];    // 6144 B
    __shared__ __align__(16) __half Bsl[2][KC][CPAD];    // 6144 B  (total 45056)

    int n   = blockIdx.z;
    int spl = blockIdx.y;
    int p0  = blockIdx.x * BM;
    int ks0 = spl * KRANGE;
    int tid = threadIdx.x;
    int warp = tid >> 5, lane = tid & 31;

    const __half* Khb = d_Kh + (size_t)n * PP * PP;
    const __half* Klb = d_Kl + (size_t)n * PP * PP;
    const __half* Vhb = d_Vh + (size_t)n * PP * CPAD;
    const __half* Vlb = d_Vl + (size_t)n * PP * CPAD;

    float acc[3][4];
    #pragma unroll
    for (int i = 0; i < 3; ++i)
        #pragma unroll
        for (int j = 0; j < 4; ++j) acc[i][j] = 0.f;

    auto load_stage = [&](int chunk, int buf) {
        int q0 = ks0 + chunk * KC;
        #pragma unroll
        for (int i = 0; i < 4; ++i) {               // A: 64 rows x 8 segs(16B) x {h,l}
            int idx = tid * 4 + i;                  // 0..511
            int row = idx >> 3, seg = idx & 7;
            int pseg = seg ^ (row & 7);             // XOR swizzle
            const __half* gh = Khb + (size_t)(p0 + row) * PP + q0 + seg * 8;
            const __half* gl = Klb + (size_t)(p0 + row) * PP + q0 + seg * 8;
            CP_ASYNC16((uint32_t)__cvta_generic_to_shared(&Ash[buf][row][pseg * 8]), gh);
            CP_ASYNC16((uint32_t)__cvta_generic_to_shared(&Asl[buf][row][pseg * 8]), gl);
        }
        #pragma unroll
        for (int i = 0; i < 2; ++i) {               // B: 64*24 halves = 192 segs x {h,l}
            int idx = tid * 2 + i;
            if (idx < 192) {
                const __half* gh = Vhb + (size_t)q0 * CPAD + idx * 8;
                const __half* gl = Vlb + (size_t)q0 * CPAD + idx * 8;
                CP_ASYNC16((uint32_t)__cvta_generic_to_shared(&Bsh[buf][0][0] + idx * 8), gh);
                CP_ASYNC16((uint32_t)__cvta_generic_to_shared(&Bsl[buf][0][0] + idx * 8), gl);
            }
        }
    };

    load_stage(0, 0);
    CP_COMMIT();

    for (int ch = 0; ch < NCH; ++ch) {
        int buf = ch & 1;
        if (ch + 1 < NCH) load_stage(ch + 1, buf ^ 1);
        CP_COMMIT();
        CP_WAIT1();
        __syncthreads();

        int m0 = warp * 16;
        #pragma unroll
        for (int kk = 0; kk < KC / 16; ++kk) {
            int arow = m0 + (lane & 15);
            int aseg = (kk * 2 + (lane >> 4)) ^ (arow & 7);   // swizzled segment
            uint32_t ah0, ah1, ah2, ah3, al0, al1, al2, al3;
            uint32_t aaddr_h = (uint32_t)__cvta_generic_to_shared(&Ash[buf][arow][aseg * 8]);
            uint32_t aaddr_l = (uint32_t)__cvta_generic_to_shared(&Asl[buf][arow][aseg * 8]);
            asm volatile("ldmatrix.sync.aligned.m8n8.x4.shared.b16 {%0,%1,%2,%3}, [%4];"
                         : "=r"(ah0), "=r"(ah1), "=r"(ah2), "=r"(ah3) : "r"(aaddr_h));
            asm volatile("ldmatrix.sync.aligned.m8n8.x4.shared.b16 {%0,%1,%2,%3}, [%4];"
                         : "=r"(al0), "=r"(al1), "=r"(al2), "=r"(al3) : "r"(aaddr_l));
            #pragma unroll
            for (int nt = 0; nt < 3; ++nt) {
                uint32_t bh0, bh1, bl0, bl1;
                uint32_t baddr_h = (uint32_t)__cvta_generic_to_shared(
                    &Bsh[buf][kk * 16 + (lane & 15)][nt * 8]);
                uint32_t baddr_l = (uint32_t)__cvta_generic_to_shared(
                    &Bsl[buf][kk * 16 + (lane & 15)][nt * 8]);
                asm volatile("ldmatrix.sync.aligned.m8n8.x2.trans.shared.b16 {%0,%1}, [%2];"
                             : "=r"(bh0), "=r"(bh1) : "r"(baddr_h));
                asm volatile("ldmatrix.sync.aligned.m8n8.x2.trans.shared.b16 {%0,%1}, [%2];"
                             : "=r"(bl0), "=r"(bl1) : "r"(baddr_l));
                asm volatile(
                    "mma.sync.aligned.m16n8k16.row.col.f32.f16.f16.f32 "
                    "{%0,%1,%2,%3}, {%4,%5,%6,%7}, {%8,%9}, {%0,%1,%2,%3};"
                    : "+f"(acc[nt][0]), "+f"(acc[nt][1]), "+f"(acc[nt][2]), "+f"(acc[nt][3])
                    : "r"(ah0), "r"(ah1), "r"(ah2), "r"(ah3), "r"(bh0), "r"(bh1));
                asm volatile(
                    "mma.sync.aligned.m16n8k16.row.col.f32.f16.f16.f32 "
                    "{%0,%1,%2,%3}, {%4,%5,%6,%7}, {%8,%9}, {%0,%1,%2,%3};"
                    : "+f"(acc[nt][0]), "+f"(acc[nt][1]), "+f"(acc[nt][2]), "+f"(acc[nt][3])
                    : "r"(ah0), "r"(ah1), "r"(ah2), "r"(ah3), "r"(bl0), "r"(bl1));
                asm volatile(
                    "mma.sync.aligned.m16n8k16.row.col.f32.f16.f16.f32 "
                    "{%0,%1,%2,%3}, {%4,%5,%6,%7}, {%8,%9}, {%0,%1,%2,%3};"
                    : "+f"(acc[nt][0]), "+f"(acc[nt][1]), "+f"(acc[nt][2]), "+f"(acc[nt][3])
                    : "r"(al0), "r"(al1), "r"(al2), "r"(al3), "r"(bh0), "r"(bh1));
            }
        }
        __syncthreads();
    }

    // epilogue: scatter partials
    float* qbf = d_qbfp + ((size_t)(spl * NB + n) * CC) * PP;
    int prow = p0 + warp * 16 + (lane >> 2);
    int cb = (lane & 3) * 2;
    #pragma unroll
    for (int nt = 0; nt < 3; ++nt)
        #pragma unroll
        for (int r = 0; r < 4; ++r) {
            int c = nt * 8 + cb + (r & 1);
            int p = prow + (r >> 1) * 8;
            if (c < CC) qbf[(size_t)c * PP + p] = acc[nt][r];
        }
}

// ---------------- vertical 1-D conv on q -> tmp ----------------
__global__ void vconv_kernel() {
    int idx = blockIdx.x * blockDim.x + threadIdx.x;
    if (idx >= NB * CC * PP) return;
    int x = idx & 63, y = (idx >> 6) & 63, nc = idx >> 12;
    const float* base = d_q + (size_t)nc * PP;
    int dlo = (35 - y) > 0 ? (35 - y) : 0;
    int dhi = (98 - y) < 70 ? (98 - y) : 70;
    float acc = 0.f;
    for (int d = dlo; d <= dhi; ++d)
        acc += d_g1d[d] * base[(y + d - KR) * WW + x];
    d_tmp[idx] = acc;
}

// ---------------- horizontal conv + combine + softmax ----------------
__global__ __launch_bounds__(64) void hcombine_kernel(float* __restrict__ outp, int write_out) {
    __shared__ float row[CC][WW + 2 * KR];   // zero-padded rows
    __shared__ float g[KS];
    int bn = blockIdx.x;
    int n = bn >> 6, y = bn & 63;
    int x = threadIdx.x;

    for (int i = x; i < KS; i += 64) g[i] = d_g1d[i];
    #pragma unroll
    for (int c = 0; c < CC; ++c) {
        row[c][KR + x] = d_tmp[((size_t)n * CC + c) * PP + y * WW + x];
        if (x < KR) { row[c][x] = 0.f; row[c][KR + WW + x] = 0.f; }
    }
    __syncthreads();

    const size_t SPL = (size_t)NB * CC * PP;
    const float* Ub = d_U    + (size_t)n * CC * PP + y * WW + x;
    const float* Qb = d_qbfp + (size_t)n * CC * PP + y * WW + x;
    float lg[CC];
    float m = -1e30f;
    #pragma unroll
    for (int c = 0; c < CC; ++c) {
        float s = 0.f;
        #pragma unroll 7
        for (int d = 0; d < KS; ++d) s += g[d] * row[c][x + d];
        float qb = Qb[(size_t)c * PP] + Qb[SPL + (size_t)c * PP]
                 + Qb[2 * SPL + (size_t)c * PP] + Qb[3 * SPL + (size_t)c * PP];
        float v = Ub[(size_t)c * PP] + 4.0f * qb + 2.0f * s;
        lg[c] = v;
        m = fmaxf(m, v);
    }
    float ssum = 0.f;
    #pragma unroll
    for (int c = 0; c < CC; ++c) { float e = expf(lg[c] - m); lg[c] = e; ssum += e; }
    float inv = 1.f / ssum;
    __half* vh = d_Vh + ((size_t)n * PP + y * WW + x) * CPAD;
    __half* vl = d_Vl + ((size_t)n * PP + y * WW + x) * CPAD;
    #pragma unroll
    for (int c = 0; c < CC; ++c) {
        float qv = lg[c] * inv;
        size_t o = ((size_t)n * CC + c) * PP + y * WW + x;
        d_q[o] = qv;
        split_half(qv, vh[c], vl[c]);
        if (write_out) outp[o] = qv;
    }
}

// ---------------- launch ----------------
extern "C" void kernel_launch(void* const* d_in, const int* in_sizes, int n_in,
                              void* d_out, int out_size) {
    const float* unary = (const float*)d_in[0];
    const float* ref   = (const float*)d_in[1];
    const float* gk    = (const float*)d_in[2];
    const float* kstd  = (const float*)d_in[3];
    float* out = (float*)d_out;

    feats_kernel<<<(NB * PP + 255) / 256, 256>>>(ref, kstd);
    g1d_kernel<<<1, 128>>>(gk);
    init_kernel<<<(NB * PP + 255) / 256, 256>>>(unary);
    buildK_kernel<<<dim3(PP / 128, PP / 32, NB), dim3(64, 4)>>>();

    for (int it = 0; it < 5; ++it) {
        vconv_kernel<<<(NB * CC * PP + 255) / 256, 256>>>();
        gemm_kernel<<<dim3(PP / BM, SPLITS, NB), 128>>>();
        hcombine_kernel<<<NB * HH, 64>>>(out, it == 4 ? 1 : 0);
    }
}